// round 3
// baseline (speedup 1.0000x reference)
#include <cuda_runtime.h>
#include <math.h>

// ---------------- problem constants ----------------
constexpr int L = 2048;
constexpr int B = 8;
constexpr int D = 1024;
constexpr int Z = 128;
constexpr int H = 2048;
constexpr int NSTATE = 16;
constexpr int MAXP = 2048;
constexpr int MLB = L * B;                 // 16384 rows
constexpr int NBASE = D + Z + H + D;       // 4224 = 33*128

// ---------------- scratch (device globals; no allocation) ----------------
__device__ float g_xn[(size_t)MLB * D];
__device__ float g_mx[(size_t)MLB * D];
__device__ float g_v[(size_t)MLB * H];
__device__ float g_u[(size_t)MLB * D];
__device__ float g_zb[(size_t)MLB * Z];
__device__ float g_r[(size_t)MLB * H];
__device__ float g_hx[(size_t)MLB * D];
__device__ float g_q[(size_t)B * L * Z];
__device__ float g_kT[(size_t)B * Z * L];
__device__ float g_attn[(size_t)B * L * L];
__device__ float g_hr[(size_t)MLB * H];        // (attn@v)*r, rows l*B+b
__device__ float g_eq[D * NSTATE];
__device__ float g_ew[D * NSTATE];

// ---------------- small helpers ----------------
__device__ __forceinline__ float siluf(float x) { return x / (1.0f + __expf(-x)); }
__device__ __forceinline__ float sigmf(float x) { return 1.0f / (1.0f + __expf(-x)); }

__device__ __forceinline__ unsigned f2tf(float x) {
    unsigned r;
    asm("cvt.rna.tf32.f32 %0, %1;" : "=r"(r) : "f"(x));
    return r;
}

__device__ __forceinline__ void mma8(float* d, const unsigned* a, const unsigned* b) {
    asm volatile(
        "mma.sync.aligned.m16n8k8.row.col.f32.tf32.tf32.f32 "
        "{%0,%1,%2,%3}, {%4,%5,%6,%7}, {%8,%9}, {%0,%1,%2,%3};"
        : "+f"(d[0]), "+f"(d[1]), "+f"(d[2]), "+f"(d[3])
        : "r"(a[0]), "r"(a[1]), "r"(a[2]), "r"(a[3]), "r"(b[0]), "r"(b[1]));
}

__device__ __forceinline__ float blockSum(float v, float* sh) {
    int t = threadIdx.x, lane = t & 31, wid = t >> 5;
#pragma unroll
    for (int o = 16; o; o >>= 1) v += __shfl_xor_sync(0xffffffffu, v, o);
    if (lane == 0) sh[wid] = v;
    __syncthreads();
    if (wid == 0) {
        float s = (lane < 8) ? sh[lane] : 0.0f;
#pragma unroll
        for (int o = 4; o; o >>= 1) s += __shfl_xor_sync(0xffffffffu, s, o);
        if (lane == 0) sh[0] = s;
    }
    __syncthreads();
    float r = sh[0];
    __syncthreads();
    return r;
}

// ---------------- EMA parameter precompute ----------------
__global__ void ema_params_k(const float* __restrict__ delta, const float* __restrict__ alpha,
                             const float* __restrict__ beta, const float* __restrict__ gamma) {
    int i = blockIdx.x * blockDim.x + threadIdx.x;
    if (i >= D * NSTATE) return;
    float p = 1.0f / (1.0f + expf(-delta[i]));
    float q = 1.0f - p * (1.0f / (1.0f + expf(-alpha[i])));
    g_eq[i] = q;
    g_ew[i] = p * beta[i] * gamma[i] * 0.25f;   // scale = 1/sqrt(16)
}

// ---------------- LayerNorm ----------------
__global__ void layernorm_k(const float* __restrict__ x, const float* __restrict__ w,
                            const float* __restrict__ bb) {
    __shared__ float sh[8];
    const int row = blockIdx.x;
    const int t = threadIdx.x;
    const float4 v = ((const float4*)(x + (size_t)row * D))[t];
    float s = (v.x + v.y) + (v.z + v.w);
    s = blockSum(s, sh);
    const float mu = s * (1.0f / D);
    float dx = v.x - mu, dy = v.y - mu, dz = v.z - mu, dw = v.w - mu;
    float sq = dx * dx + dy * dy + dz * dz + dw * dw;
    sq = blockSum(sq, sh);
    const float inv = rsqrtf(sq * (1.0f / D) + 1e-5f);
    const float4 wv = ((const float4*)w)[t];
    const float4 bv = ((const float4*)bb)[t];
    float4 o;
    o.x = dx * inv * wv.x + bv.x;
    o.y = dy * inv * wv.y + bv.y;
    o.z = dz * inv * wv.z + bv.z;
    o.w = dw * inv * wv.w + bv.w;
    ((float4*)(g_xn + (size_t)row * D))[t] = o;
}

// ---------------- EMA scan ----------------
__global__ void ema_scan_k(const float* __restrict__ omega) {
    int t = blockIdx.x * blockDim.x + threadIdx.x;   // B*D threads
    int b = t / D, d = t % D;
    float q[NSTATE], w[NSTATE], s[NSTATE];
    const float4* q4 = (const float4*)(g_eq + d * NSTATE);
    const float4* w4 = (const float4*)(g_ew + d * NSTATE);
#pragma unroll
    for (int n = 0; n < NSTATE / 4; n++) {
        float4 a = q4[n];
        q[4 * n + 0] = a.x; q[4 * n + 1] = a.y; q[4 * n + 2] = a.z; q[4 * n + 3] = a.w;
        float4 c = w4[n];
        w[4 * n + 0] = c.x; w[4 * n + 1] = c.y; w[4 * n + 2] = c.z; w[4 * n + 3] = c.w;
    }
#pragma unroll
    for (int n = 0; n < NSTATE; n++) s[n] = 0.0f;
    const float om = omega[d];
    const float* xp = g_xn + (size_t)b * D + d;
    float* mp = g_mx + (size_t)b * D + d;
    const size_t stride = (size_t)B * D;
#pragma unroll 8
    for (int l = 0; l < L; l++) {
        float xv = xp[(size_t)l * stride];
        float y0 = 0.f, y1 = 0.f, y2 = 0.f, y3 = 0.f;
#pragma unroll
        for (int n = 0; n < NSTATE; n++) s[n] = fmaf(q[n], s[n], xv);
#pragma unroll
        for (int n = 0; n < NSTATE; n += 4) {
            y0 = fmaf(w[n + 0], s[n + 0], y0);
            y1 = fmaf(w[n + 1], s[n + 1], y1);
            y2 = fmaf(w[n + 2], s[n + 2], y2);
            y3 = fmaf(w[n + 3], s[n + 3], y3);
        }
        float c = (y0 + y1) + (y2 + y3);
        c = fmaf(xv, om, c);
        mp[(size_t)l * stride] = siluf(c);
    }
}

// ---------------- q/k build from z ----------------
__global__ void qk_k(const float* __restrict__ qg, const float* __restrict__ qb) {
    int i = blockIdx.x * blockDim.x + threadIdx.x;   // MLB*Z threads
    int z = i % Z;
    int row = i / Z;                                  // l*B + b
    int l = row / B, b = row % B;
    float zv = g_zb[i];
    g_q[((size_t)b * L + l) * Z + z] = fmaf(zv, qg[z], qb[z]);
    g_kT[((size_t)b * Z + z) * L + l] = fmaf(zv, qg[Z + z], qb[Z + z]);
}

// ============================================================================
// 3xTF32 tensor-core GEMM. Block tile 128x128, BK=8, 8 warps (2m x 4n),
// warp tile 64x32 = 4x4 m16n8 mma tiles. A/B staged in smem as split hi/lo
// tf32 planes, double-buffered. D = C accumulated in fp32.
// MODE epilogues: 0=v, 1=base split, 2=qk->laplace, 3=attn@v*r, 4=final
// ============================================================================
constexpr int BM = 128, BN = 128, BK = 8;
constexpr int SPAD = BM + 8;   // padded smem row

template <int MODE>
__device__ __forceinline__ void gemm_body(const float* __restrict__ A, const float* __restrict__ Bm,
                                          int lda, int ldb, long sA, long sB, int K,
                                          const float* __restrict__ ebias,
                                          const float* __restrict__ ex,
                                          float* __restrict__ eout) {
    __shared__ unsigned AsH[2][BK][SPAD];
    __shared__ unsigned AsL[2][BK][SPAD];
    __shared__ unsigned BsH[2][BK][SPAD];
    __shared__ unsigned BsL[2][BK][SPAD];

    const int bz = blockIdx.z;
    A += sA * bz;
    Bm += sB * bz;
    const int bm = blockIdx.y * BM, bn = blockIdx.x * BN;
    const int t = threadIdx.x;
    const int lane = t & 31, wid = t >> 5;
    const int gid = lane >> 2, tig = lane & 3;
    const int warpM = (wid >> 2) << 6;   // 0 / 64
    const int warpN = (wid & 3) << 5;    // 0/32/64/96

    // staging indices: A: 128 rows x 8k = 1024 floats = 1 float4/thread
    const int aRow = t >> 1, aK = (t & 1) << 2;
    const float* ap = A + (size_t)(bm + aRow) * lda + aK;
    // B: 8k x 128n = 1024 floats = 1 float4/thread
    const int bRow = t >> 5, bCol = (t & 31) << 2;
    const float* bp = Bm + (size_t)bRow * ldb + bn + bCol;
    const size_t bStep = (size_t)BK * ldb;

    float4 areg = *(const float4*)ap;
    float4 breg = *(const float4*)bp;

    float acc[4][4][4];
#pragma unroll
    for (int i = 0; i < 4; i++)
#pragma unroll
        for (int j = 0; j < 4; j++)
#pragma unroll
            for (int c = 0; c < 4; c++) acc[i][j][c] = 0.0f;

    // ---- stage buffer 0 ----
    {
        float av[4] = {areg.x, areg.y, areg.z, areg.w};
#pragma unroll
        for (int i = 0; i < 4; i++) {
            unsigned h = f2tf(av[i]);
            AsH[0][aK + i][aRow] = h;
            AsL[0][aK + i][aRow] = f2tf(av[i] - __uint_as_float(h));
        }
        float bv[4] = {breg.x, breg.y, breg.z, breg.w};
#pragma unroll
        for (int i = 0; i < 4; i++) {
            unsigned h = f2tf(bv[i]);
            BsH[0][bRow][bCol + i] = h;
            BsL[0][bRow][bCol + i] = f2tf(bv[i] - __uint_as_float(h));
        }
    }
    __syncthreads();

    const int nk = K / BK;
    int cur = 0;
    for (int kt = 0; kt < nk; ++kt) {
        if (kt + 1 < nk) {
            ap += BK;
            bp += bStep;
            areg = *(const float4*)ap;
            breg = *(const float4*)bp;
        }

        // ---- fragment loads ----
        unsigned aH[4][4], aL[4][4], bH[4][2], bL[4][2];
#pragma unroll
        for (int mt = 0; mt < 4; mt++) {
            const int m0 = warpM + mt * 16 + gid;
            aH[mt][0] = AsH[cur][tig][m0];
            aH[mt][1] = AsH[cur][tig][m0 + 8];
            aH[mt][2] = AsH[cur][tig + 4][m0];
            aH[mt][3] = AsH[cur][tig + 4][m0 + 8];
            aL[mt][0] = AsL[cur][tig][m0];
            aL[mt][1] = AsL[cur][tig][m0 + 8];
            aL[mt][2] = AsL[cur][tig + 4][m0];
            aL[mt][3] = AsL[cur][tig + 4][m0 + 8];
        }
#pragma unroll
        for (int nt = 0; nt < 4; nt++) {
            const int n0 = warpN + nt * 8 + gid;
            bH[nt][0] = BsH[cur][tig][n0];
            bH[nt][1] = BsH[cur][tig + 4][n0];
            bL[nt][0] = BsL[cur][tig][n0];
            bL[nt][1] = BsL[cur][tig + 4][n0];
        }

        // ---- 16 base tiles x 3 split terms ----
#pragma unroll
        for (int mt = 0; mt < 4; mt++)
#pragma unroll
            for (int nt = 0; nt < 4; nt++) {
                mma8(acc[mt][nt], aH[mt], bH[nt]);
                mma8(acc[mt][nt], aH[mt], bL[nt]);
                mma8(acc[mt][nt], aL[mt], bH[nt]);
            }

        if (kt + 1 < nk) {
            int nxt = cur ^ 1;
            float av[4] = {areg.x, areg.y, areg.z, areg.w};
#pragma unroll
            for (int i = 0; i < 4; i++) {
                unsigned h = f2tf(av[i]);
                AsH[nxt][aK + i][aRow] = h;
                AsL[nxt][aK + i][aRow] = f2tf(av[i] - __uint_as_float(h));
            }
            float bv[4] = {breg.x, breg.y, breg.z, breg.w};
#pragma unroll
            for (int i = 0; i < 4; i++) {
                unsigned h = f2tf(bv[i]);
                BsH[nxt][bRow][bCol + i] = h;
                BsL[nxt][bRow][bCol + i] = f2tf(bv[i] - __uint_as_float(h));
            }
        }
        __syncthreads();
        cur ^= 1;
    }

    // ---- epilogue: acc[mt][nt]{d0,d1,d2,d3} ----
#pragma unroll
    for (int mt = 0; mt < 4; mt++) {
#pragma unroll
        for (int nt = 0; nt < 4; nt++) {
#pragma unroll
            for (int half = 0; half < 2; half++) {       // d0/d1 then d2/d3
                const int row = bm + warpM + mt * 16 + gid + half * 8;
#pragma unroll
                for (int c = 0; c < 2; c++) {
                    const int col = bn + warpN + nt * 8 + 2 * tig + c;
                    float v = acc[mt][nt][half * 2 + c];
                    if constexpr (MODE == 0) {
                        v += ebias[col];
                        g_v[(size_t)row * H + col] = siluf(v);
                    } else if constexpr (MODE == 1) {
                        v += ebias[col];
                        if (col < D) g_u[(size_t)row * D + col] = sigmf(v);
                        else if (col < D + Z) g_zb[(size_t)row * Z + (col - D)] = siluf(v);
                        else if (col < D + Z + H) g_r[(size_t)row * H + (col - (D + Z))] = siluf(v);
                        else g_hx[(size_t)row * D + (col - (D + Z + H))] = v;
                    } else if constexpr (MODE == 2) {
                        float tq = v * (1.0f / (float)L) + ebias[MAXP - 1 + col - row];
                        g_attn[(size_t)bz * L * L + (size_t)row * L + col] =
                            0.5f * (1.0f + erff((tq - 0.70710700f) * 2.50662827f));
                    } else if constexpr (MODE == 3) {
                        size_t o = ((size_t)row * B + bz) * H + col;
                        g_hr[o] = v * g_r[o];
                    } else {
                        v += ebias[col] + g_hx[(size_t)row * D + col];
                        float sv = siluf(v);
                        float xv = ex[(size_t)row * D + col];
                        eout[(size_t)row * D + col] = xv + g_u[(size_t)row * D + col] * (sv - xv);
                    }
                }
            }
        }
    }
}

__global__ void __launch_bounds__(256, 1) gemm_v_k(const float* __restrict__ vw,
                                                   const float* __restrict__ vb) {
    gemm_body<0>(g_xn, vw, D, H, 0, 0, D, vb, nullptr, nullptr);
}
__global__ void __launch_bounds__(256, 1) gemm_base_k(const float* __restrict__ mxw,
                                                      const float* __restrict__ mxb) {
    gemm_body<1>(g_mx, mxw, D, NBASE, 0, 0, D, mxb, nullptr, nullptr);
}
__global__ void __launch_bounds__(256, 1) gemm_qk_k(const float* __restrict__ rel) {
    gemm_body<2>(g_q, g_kT, Z, L, (long)L * Z, (long)Z * L, Z, rel, nullptr, nullptr);
}
__global__ void __launch_bounds__(256, 1) gemm_av_k() {
    gemm_body<3>(g_attn, g_v, L, B * H, (long)L * L, (long)H, L, nullptr, nullptr, nullptr);
}
__global__ void __launch_bounds__(256, 1) gemm_out_k(const float* __restrict__ hw,
                                                     const float* __restrict__ hb,
                                                     const float* __restrict__ x,
                                                     float* __restrict__ out) {
    gemm_body<4>(g_hr, hw, H, D, 0, 0, H, hb, x, out);
}

// ---------------- launch ----------------
extern "C" void kernel_launch(void* const* d_in, const int* in_sizes, int n_in,
                              void* d_out, int out_size) {
    const float* x       = (const float*)d_in[0];
    const float* delta   = (const float*)d_in[1];
    const float* alpha   = (const float*)d_in[2];
    const float* beta_e  = (const float*)d_in[3];
    const float* gamma_e = (const float*)d_in[4];
    const float* omega   = (const float*)d_in[5];
    const float* v_w     = (const float*)d_in[6];
    const float* v_b     = (const float*)d_in[7];
    const float* mx_w    = (const float*)d_in[8];
    const float* mx_b    = (const float*)d_in[9];
    const float* h_w     = (const float*)d_in[10];
    const float* h_b     = (const float*)d_in[11];
    const float* qk_g    = (const float*)d_in[12];
    const float* qk_b    = (const float*)d_in[13];
    const float* rel     = (const float*)d_in[14];
    const float* ln_w    = (const float*)d_in[15];
    const float* ln_b    = (const float*)d_in[16];
    float* out = (float*)d_out;

    ema_params_k<<<(D * NSTATE + 255) / 256, 256>>>(delta, alpha, beta_e, gamma_e);
    layernorm_k<<<MLB, 256>>>(x, ln_w, ln_b);
    ema_scan_k<<<(B * D) / 256, 256>>>(omega);

    gemm_v_k<<<dim3(H / BN, MLB / BM, 1), 256>>>(v_w, v_b);
    gemm_base_k<<<dim3(NBASE / BN, MLB / BM, 1), 256>>>(mx_w, mx_b);

    qk_k<<<(MLB * Z) / 256, 256>>>(qk_g, qk_b);

    gemm_qk_k<<<dim3(L / BN, L / BM, B), 256>>>(rel);
    gemm_av_k<<<dim3(H / BN, L / BM, B), 256>>>();
    gemm_out_k<<<dim3(D / BN, MLB / BM, 1), 256>>>(h_w, h_b, x, out);
}

// round 7
// speedup vs baseline: 1.6436x; 1.6436x over previous
#include <cuda_runtime.h>
#include <math.h>

// ---------------- problem constants ----------------
constexpr int L = 2048;
constexpr int B = 8;
constexpr int D = 1024;
constexpr int Z = 128;
constexpr int H = 2048;
constexpr int NSTATE = 16;
constexpr int MAXP = 2048;
constexpr int MLB = L * B;                 // 16384 rows
constexpr int NBASE = D + Z + H + D;       // 4224 = 33*128

// ---------------- scratch (device globals; no allocation) ----------------
__device__ float g_xn[(size_t)MLB * D];
__device__ float g_mx[(size_t)MLB * D];
__device__ float g_v[(size_t)MLB * H];
__device__ float g_u[(size_t)MLB * D];
__device__ float g_zb[(size_t)MLB * Z];
__device__ float g_r[(size_t)MLB * H];
__device__ float g_hx[(size_t)MLB * D];
__device__ float g_q[(size_t)B * L * Z];
__device__ float g_kT[(size_t)B * Z * L];
__device__ float g_attn[(size_t)B * L * L];
__device__ float g_hr[(size_t)MLB * H];        // (attn@v)*r, rows l*B+b
__device__ float g_eq[D * NSTATE];
__device__ float g_ew[D * NSTATE];

// ---------------- small helpers ----------------
__device__ __forceinline__ float siluf(float x) { return x / (1.0f + __expf(-x)); }
__device__ __forceinline__ float sigmf(float x) { return 1.0f / (1.0f + __expf(-x)); }

__device__ __forceinline__ unsigned f2tf(float x) {
    unsigned r;
    asm("cvt.rna.tf32.f32 %0, %1;" : "=r"(r) : "f"(x));
    return r;
}

__device__ __forceinline__ void mma8(float* d, const unsigned* a, unsigned b0, unsigned b1) {
    asm volatile(
        "mma.sync.aligned.m16n8k8.row.col.f32.tf32.tf32.f32 "
        "{%0,%1,%2,%3}, {%4,%5,%6,%7}, {%8,%9}, {%0,%1,%2,%3};"
        : "+f"(d[0]), "+f"(d[1]), "+f"(d[2]), "+f"(d[3])
        : "r"(a[0]), "r"(a[1]), "r"(a[2]), "r"(a[3]), "r"(b0), "r"(b1));
}

__device__ __forceinline__ float blockSum(float v, float* sh) {
    int t = threadIdx.x, lane = t & 31, wid = t >> 5;
#pragma unroll
    for (int o = 16; o; o >>= 1) v += __shfl_xor_sync(0xffffffffu, v, o);
    if (lane == 0) sh[wid] = v;
    __syncthreads();
    if (wid == 0) {
        float s = (lane < 8) ? sh[lane] : 0.0f;
#pragma unroll
        for (int o = 4; o; o >>= 1) s += __shfl_xor_sync(0xffffffffu, s, o);
        if (lane == 0) sh[0] = s;
    }
    __syncthreads();
    float r = sh[0];
    __syncthreads();
    return r;
}

// ---------------- EMA parameter precompute ----------------
__global__ void ema_params_k(const float* __restrict__ delta, const float* __restrict__ alpha,
                             const float* __restrict__ beta, const float* __restrict__ gamma) {
    int i = blockIdx.x * blockDim.x + threadIdx.x;
    if (i >= D * NSTATE) return;
    float p = 1.0f / (1.0f + expf(-delta[i]));
    float q = 1.0f - p * (1.0f / (1.0f + expf(-alpha[i])));
    g_eq[i] = q;
    g_ew[i] = p * beta[i] * gamma[i] * 0.25f;   // scale = 1/sqrt(16)
}

// ---------------- LayerNorm ----------------
__global__ void layernorm_k(const float* __restrict__ x, const float* __restrict__ w,
                            const float* __restrict__ bb) {
    __shared__ float sh[8];
    const int row = blockIdx.x;
    const int t = threadIdx.x;
    const float4 v = ((const float4*)(x + (size_t)row * D))[t];
    float s = (v.x + v.y) + (v.z + v.w);
    s = blockSum(s, sh);
    const float mu = s * (1.0f / D);
    float dx = v.x - mu, dy = v.y - mu, dz = v.z - mu, dw = v.w - mu;
    float sq = dx * dx + dy * dy + dz * dz + dw * dw;
    sq = blockSum(sq, sh);
    const float inv = rsqrtf(sq * (1.0f / D) + 1e-5f);
    const float4 wv = ((const float4*)w)[t];
    const float4 bv = ((const float4*)bb)[t];
    float4 o;
    o.x = dx * inv * wv.x + bv.x;
    o.y = dy * inv * wv.y + bv.y;
    o.z = dz * inv * wv.z + bv.z;
    o.w = dw * inv * wv.w + bv.w;
    ((float4*)(g_xn + (size_t)row * D))[t] = o;
}

// ---------------- EMA scan ----------------
__global__ void ema_scan_k(const float* __restrict__ omega) {
    int t = blockIdx.x * blockDim.x + threadIdx.x;   // B*D threads
    int b = t / D, d = t % D;
    float q[NSTATE], w[NSTATE], s[NSTATE];
    const float4* q4 = (const float4*)(g_eq + d * NSTATE);
    const float4* w4 = (const float4*)(g_ew + d * NSTATE);
#pragma unroll
    for (int n = 0; n < NSTATE / 4; n++) {
        float4 a = q4[n];
        q[4 * n + 0] = a.x; q[4 * n + 1] = a.y; q[4 * n + 2] = a.z; q[4 * n + 3] = a.w;
        float4 c = w4[n];
        w[4 * n + 0] = c.x; w[4 * n + 1] = c.y; w[4 * n + 2] = c.z; w[4 * n + 3] = c.w;
    }
#pragma unroll
    for (int n = 0; n < NSTATE; n++) s[n] = 0.0f;
    const float om = omega[d];
    const float* xp = g_xn + (size_t)b * D + d;
    float* mp = g_mx + (size_t)b * D + d;
    const size_t stride = (size_t)B * D;
#pragma unroll 8
    for (int l = 0; l < L; l++) {
        float xv = xp[(size_t)l * stride];
        float y0 = 0.f, y1 = 0.f, y2 = 0.f, y3 = 0.f;
#pragma unroll
        for (int n = 0; n < NSTATE; n++) s[n] = fmaf(q[n], s[n], xv);
#pragma unroll
        for (int n = 0; n < NSTATE; n += 4) {
            y0 = fmaf(w[n + 0], s[n + 0], y0);
            y1 = fmaf(w[n + 1], s[n + 1], y1);
            y2 = fmaf(w[n + 2], s[n + 2], y2);
            y3 = fmaf(w[n + 3], s[n + 3], y3);
        }
        float c = (y0 + y1) + (y2 + y3);
        c = fmaf(xv, om, c);
        mp[(size_t)l * stride] = siluf(c);
    }
}

// ---------------- q/k build from z ----------------
__global__ void qk_k(const float* __restrict__ qg, const float* __restrict__ qb) {
    int i = blockIdx.x * blockDim.x + threadIdx.x;   // MLB*Z threads
    int z = i % Z;
    int row = i / Z;                                  // l*B + b
    int l = row / B, b = row % B;
    float zv = g_zb[i];
    g_q[((size_t)b * L + l) * Z + z] = fmaf(zv, qg[z], qb[z]);
    g_kT[((size_t)b * Z + z) * L + l] = fmaf(zv, qg[Z + z], qb[Z + z]);
}

// ============================================================================
// 2-term-split TF32 tensor-core GEMM (A hi-only, B hi+lo; error ~ea*b ~ 2e-4).
// Block tile 128x128, BK=8, 8 warps (2m x 4n), warp tile 64x32.
// A staged as one tf32 plane [k][m]; B staged interleaved (hi,lo) pairs
// [k][2n] for ld.shared.v2 fragment loads. Double-buffered. 2 CTAs/SM.
// MODE epilogues: 0=v, 1=base split, 2=qk->laplace, 3=attn@v*r, 4=final
// ============================================================================
constexpr int BM = 128, BN = 128, BK = 8;
constexpr int SPAD = BM + 8;        // A plane padded row
constexpr int BPADI = 2 * BN + 8;   // B interleaved padded row

template <int MODE>
__device__ __forceinline__ void gemm_body(const float* __restrict__ A, const float* __restrict__ Bm,
                                          int lda, int ldb, long sA, long sB, int K,
                                          const float* __restrict__ ebias,
                                          const float* __restrict__ ex,
                                          float* __restrict__ eout) {
    __shared__ unsigned AsH[2][BK][SPAD];
    __shared__ unsigned BsI[2][BK][BPADI];

    const int bz = blockIdx.z;
    A += sA * bz;
    Bm += sB * bz;
    const int bm = blockIdx.y * BM, bn = blockIdx.x * BN;
    const int t = threadIdx.x;
    const int lane = t & 31, wid = t >> 5;
    const int gid = lane >> 2, tig = lane & 3;
    const int warpM = (wid >> 2) << 6;   // 0 / 64
    const int warpN = (wid & 3) << 5;    // 0/32/64/96

    // staging: A 128x8 = 1024 floats, 1 float4/thread
    const int aRow = t >> 1, aK = (t & 1) << 2;
    const float* ap = A + (size_t)(bm + aRow) * lda + aK;
    // B 8x128 = 1024 floats, 1 float4/thread (coalesced global)
    const int bRow = t >> 5, bCol = (t & 31) << 2;
    const float* bp = Bm + (size_t)bRow * ldb + bn + bCol;
    const size_t bStep = (size_t)BK * ldb;

    float4 areg = *(const float4*)ap;
    float4 breg = *(const float4*)bp;

    float acc[4][4][4];
#pragma unroll
    for (int i = 0; i < 4; i++)
#pragma unroll
        for (int j = 0; j < 4; j++)
#pragma unroll
            for (int c = 0; c < 4; c++) acc[i][j][c] = 0.0f;

    // ---- stage buffer 0 ----
    {
        float av[4] = {areg.x, areg.y, areg.z, areg.w};
#pragma unroll
        for (int i = 0; i < 4; i++) AsH[0][aK + i][aRow] = f2tf(av[i]);
        float bv[4] = {breg.x, breg.y, breg.z, breg.w};
        unsigned h[4], lo[4];
#pragma unroll
        for (int i = 0; i < 4; i++) {
            h[i] = f2tf(bv[i]);
            lo[i] = f2tf(bv[i] - __uint_as_float(h[i]));
        }
        *(uint4*)&BsI[0][bRow][2 * bCol] = make_uint4(h[0], lo[0], h[1], lo[1]);
        *(uint4*)&BsI[0][bRow][2 * bCol + 4] = make_uint4(h[2], lo[2], h[3], lo[3]);
    }
    __syncthreads();

    const int nk = K / BK;
    int cur = 0;
    for (int kt = 0; kt < nk; ++kt) {
        if (kt + 1 < nk) {
            ap += BK;
            bp += bStep;
            areg = *(const float4*)ap;
            breg = *(const float4*)bp;
        }

        // ---- fragment loads ----
        unsigned aH[4][4];
        unsigned bH[4][2], bL[4][2];
#pragma unroll
        for (int mt = 0; mt < 4; mt++) {
            const int m0 = warpM + mt * 16 + gid;
            aH[mt][0] = AsH[cur][tig][m0];
            aH[mt][1] = AsH[cur][tig][m0 + 8];
            aH[mt][2] = AsH[cur][tig + 4][m0];
            aH[mt][3] = AsH[cur][tig + 4][m0 + 8];
        }
#pragma unroll
        for (int nt = 0; nt < 4; nt++) {
            const int n0 = warpN + nt * 8 + gid;
            uint2 p0 = *(const uint2*)&BsI[cur][tig][2 * n0];
            uint2 p1 = *(const uint2*)&BsI[cur][tig + 4][2 * n0];
            bH[nt][0] = p0.x; bL[nt][0] = p0.y;
            bH[nt][1] = p1.x; bL[nt][1] = p1.y;
        }

        // ---- 16 base tiles x 2 split terms ----
#pragma unroll
        for (int mt = 0; mt < 4; mt++)
#pragma unroll
            for (int nt = 0; nt < 4; nt++) {
                mma8(acc[mt][nt], aH[mt], bH[nt][0], bH[nt][1]);
                mma8(acc[mt][nt], aH[mt], bL[nt][0], bL[nt][1]);
            }

        if (kt + 1 < nk) {
            int nxt = cur ^ 1;
            float av[4] = {areg.x, areg.y, areg.z, areg.w};
#pragma unroll
            for (int i = 0; i < 4; i++) AsH[nxt][aK + i][aRow] = f2tf(av[i]);
            float bv[4] = {breg.x, breg.y, breg.z, breg.w};
            unsigned h[4], lo[4];
#pragma unroll
            for (int i = 0; i < 4; i++) {
                h[i] = f2tf(bv[i]);
                lo[i] = f2tf(bv[i] - __uint_as_float(h[i]));
            }
            *(uint4*)&BsI[nxt][bRow][2 * bCol] = make_uint4(h[0], lo[0], h[1], lo[1]);
            *(uint4*)&BsI[nxt][bRow][2 * bCol + 4] = make_uint4(h[2], lo[2], h[3], lo[3]);
        }
        __syncthreads();
        cur ^= 1;
    }

    // ---- epilogue: acc[mt][nt]{d0,d1,d2,d3} ----
#pragma unroll
    for (int mt = 0; mt < 4; mt++) {
#pragma unroll
        for (int nt = 0; nt < 4; nt++) {
#pragma unroll
            for (int half = 0; half < 2; half++) {
                const int row = bm + warpM + mt * 16 + gid + half * 8;
#pragma unroll
                for (int c = 0; c < 2; c++) {
                    const int col = bn + warpN + nt * 8 + 2 * tig + c;
                    float v = acc[mt][nt][half * 2 + c];
                    if constexpr (MODE == 0) {
                        v += ebias[col];
                        g_v[(size_t)row * H + col] = siluf(v);
                    } else if constexpr (MODE == 1) {
                        v += ebias[col];
                        if (col < D) g_u[(size_t)row * D + col] = sigmf(v);
                        else if (col < D + Z) g_zb[(size_t)row * Z + (col - D)] = siluf(v);
                        else if (col < D + Z + H) g_r[(size_t)row * H + (col - (D + Z))] = siluf(v);
                        else g_hx[(size_t)row * D + (col - (D + Z + H))] = v;
                    } else if constexpr (MODE == 2) {
                        float tq = v * (1.0f / (float)L) + ebias[MAXP - 1 + col - row];
                        g_attn[(size_t)bz * L * L + (size_t)row * L + col] =
                            0.5f * (1.0f + erff((tq - 0.70710700f) * 2.50662827f));
                    } else if constexpr (MODE == 3) {
                        size_t o = ((size_t)row * B + bz) * H + col;
                        g_hr[o] = v * g_r[o];
                    } else {
                        v += ebias[col] + g_hx[(size_t)row * D + col];
                        float sv = siluf(v);
                        float xv = ex[(size_t)row * D + col];
                        eout[(size_t)row * D + col] = xv + g_u[(size_t)row * D + col] * (sv - xv);
                    }
                }
            }
        }
    }
}

__global__ void __launch_bounds__(256, 2) gemm_v_k(const float* __restrict__ vw,
                                                   const float* __restrict__ vb) {
    gemm_body<0>(g_xn, vw, D, H, 0, 0, D, vb, nullptr, nullptr);
}
__global__ void __launch_bounds__(256, 2) gemm_base_k(const float* __restrict__ mxw,
                                                      const float* __restrict__ mxb) {
    gemm_body<1>(g_mx, mxw, D, NBASE, 0, 0, D, mxb, nullptr, nullptr);
}
__global__ void __launch_bounds__(256, 2) gemm_qk_k(const float* __restrict__ rel) {
    gemm_body<2>(g_q, g_kT, Z, L, (long)L * Z, (long)Z * L, Z, rel, nullptr, nullptr);
}
__global__ void __launch_bounds__(256, 2) gemm_av_k() {
    gemm_body<3>(g_attn, g_v, L, B * H, (long)L * L, (long)H, L, nullptr, nullptr, nullptr);
}
__global__ void __launch_bounds__(256, 2) gemm_out_k(const float* __restrict__ hw,
                                                     const float* __restrict__ hb,
                                                     const float* __restrict__ x,
                                                     float* __restrict__ out) {
    gemm_body<4>(g_hr, hw, H, D, 0, 0, H, hb, x, out);
}

// ---------------- launch ----------------
extern "C" void kernel_launch(void* const* d_in, const int* in_sizes, int n_in,
                              void* d_out, int out_size) {
    const float* x       = (const float*)d_in[0];
    const float* delta   = (const float*)d_in[1];
    const float* alpha   = (const float*)d_in[2];
    const float* beta_e  = (const float*)d_in[3];
    const float* gamma_e = (const float*)d_in[4];
    const float* omega   = (const float*)d_in[5];
    const float* v_w     = (const float*)d_in[6];
    const float* v_b     = (const float*)d_in[7];
    const float* mx_w    = (const float*)d_in[8];
    const float* mx_b    = (const float*)d_in[9];
    const float* h_w     = (const float*)d_in[10];
    const float* h_b     = (const float*)d_in[11];
    const float* qk_g    = (const float*)d_in[12];
    const float* qk_b    = (const float*)d_in[13];
    const float* rel     = (const float*)d_in[14];
    const float* ln_w    = (const float*)d_in[15];
    const float* ln_b    = (const float*)d_in[16];
    float* out = (float*)d_out;

    ema_params_k<<<(D * NSTATE + 255) / 256, 256>>>(delta, alpha, beta_e, gamma_e);
    layernorm_k<<<MLB, 256>>>(x, ln_w, ln_b);
    ema_scan_k<<<(B * D) / 256, 256>>>(omega);

    gemm_v_k<<<dim3(H / BN, MLB / BM, 1), 256>>>(v_w, v_b);
    gemm_base_k<<<dim3(NBASE / BN, MLB / BM, 1), 256>>>(mx_w, mx_b);

    qk_k<<<(MLB * Z) / 256, 256>>>(qk_g, qk_b);

    gemm_qk_k<<<dim3(L / BN, L / BM, B), 256>>>(rel);
    gemm_av_k<<<dim3(H / BN, L / BM, B), 256>>>();
    gemm_out_k<<<dim3(D / BN, MLB / BM, 1), 256>>>(h_w, h_b, x, out);
}